// round 16
// baseline (speedup 1.0000x reference)
#include <cuda_runtime.h>
#include <math.h>

#define BE 64
#define NOCT 32
#define NSAMP 32768
#define TPB 128
#define NBLK 1024                 // static: 2 items per block
#define ITEM_SAMP 1024
#define NITEMS 2048               // (be,chunk) items, be-interleaved ids
#define SPT 8
#define NF4 (BE * NSAMP / 4)      // 524288 float4

// Scratch (no allocation allowed). g_wmax slots each written exactly once per
// launch (static unique owner). Barrier state self-restores across replays
// (g_count returns to 0; g_phase keeps flipping).
__device__ float g_wmax[NITEMS];  // slot = item id (be = id & 63)
__device__ int   g_count;
__device__ volatile int g_phase;

typedef unsigned long long ull;

__device__ __forceinline__ ull pk2(float x, float y) {
    ull r;
    asm("mov.b64 %0, {%1, %2};" : "=l"(r)
        : "r"(__float_as_uint(x)), "r"(__float_as_uint(y)));
    return r;
}
__device__ __forceinline__ void upk2(ull v, float& x, float& y) {
    unsigned a, b;
    asm("mov.b64 {%0, %1}, %2;" : "=r"(a), "=r"(b) : "l"(v));
    x = __uint_as_float(a);
    y = __uint_as_float(b);
}
__device__ __forceinline__ ull f2mul(ull a, ull b) {
    ull c; asm("mul.rn.f32x2 %0, %1, %2;" : "=l"(c) : "l"(a), "l"(b)); return c;
}
__device__ __forceinline__ ull f2add(ull a, ull b) {
    ull c; asm("add.rn.f32x2 %0, %1, %2;" : "=l"(c) : "l"(a), "l"(b)); return c;
}
__device__ __forceinline__ ull f2fma(ull a, ull b, ull c) {
    ull d; asm("fma.rn.f32x2 %0, %1, %2, %3;" : "=l"(d)
               : "l"(a), "l"(b), "l"(c)); return d;
}

__device__ __forceinline__ void grid_barrier() {
    __syncthreads();
    if (threadIdx.x == 0) {
        int ph = g_phase;
        __threadfence();                           // release
        if (atomicAdd(&g_count, 1) == NBLK - 1) {
            g_count = 0;
            __threadfence();
            g_phase = ph ^ 1;
        } else {
            while (g_phase == ph) { __nanosleep(32); }
        }
        __threadfence();                           // acquire
    }
    __syncthreads();
}

// fl32(f*t) phase -> magic round -> exact 2-FMA Cody-Waite -> MUFU sin.
// Lanewise IEEE RN, bit-identical to the scalar reference path.
#define OSC_STEP(F2, A2, TPj, ACCj)                                   \
    {                                                                 \
        ull p2 = f2mul((F2), (TPj));                                  \
        ull q2 = f2fma(p2, INV2PI2, MAGIC2);                          \
        ull k2 = f2add(q2, NMAG2);                                    \
        ull r2 = f2fma(k2, NHI2, p2);                                 \
        r2     = f2fma(k2, NLO2, r2);                                 \
        float r0_, r1_; upk2(r2, r0_, r1_);                           \
        ull s2 = pk2(__sinf(r0_), __sinf(r1_));                       \
        (ACCj) = f2fma(s2, (A2), (ACCj));                             \
    }

// Process one (be, chunk) item: warp-0 setup (phase path bit-exact: lane o
// repeats the sequential f32 fadd chain of length o+1), f32x2 osc body,
// float4 stores, block max -> g_wmax[item].
__device__ __forceinline__ void do_item(
    int it, int tid, int lane,
    const float* __restrict__ f0_in,
    const float* __restrict__ dec_in,
    const float* __restrict__ sp_in,
    float* __restrict__ out,
    ull* sfp, ull* sap, int* snact, float* wm,
    ull INV2PI2, ull MAGIC2, ull NMAG2, ull NHI2, ull NLO2)
{
    const int be    = it & (BE - 1);
    const int chunk = it >> 6;                     // 0..31

    if (tid < 32) {
        const float MINF   = (float)(20.0 / 11025.0);
        const float FRANGE = (float)(3000.0 / 11025.0 - 20.0 / 11025.0);
        const float PI_F   = (float)3.14159265358979323846;
        const float RESF   = (float)((1.0 - 0.01) * 0.99);

        float f0  = fabsf(f0_in[be]);
        float fsc = __fmul_rn(__fadd_rn(MINF, __fmul_rn(f0, FRANGE)), PI_F);
        float sp  = sp_in[be];

        float x  = dec_in[be];
        float s1 = 1.0f / (1.0f + expf(-x));
        float s2 = 1.0f / (1.0f + expf(-s1));
        float d  = __fadd_rn(0.01f, __fmul_rn(s2, RESF));
        float ld = logf(__fadd_rn(d, 1e-12f));

        float fac = 0.0f;
        #pragma unroll
        for (int i = 0; i < NOCT; i++)
            if (i <= lane) fac = __fadd_rn(fac, sp);   // predicated seq cumsum
        float f0s = __fmul_rn(fsc, fac);
        float amp = __expf((float)(lane + 1) * ld);    // amp err ~1e-6, safe
        sfp[lane] = pk2(f0s, f0s);
        sap[lane] = pk2(amp, amp);
        unsigned bal = __ballot_sync(0xFFFFFFFFu, f0s < 1.0f);
        if (lane == 0) *snact = __popc(bal);           // monotone prefix mask
    }
    __syncthreads();
    const int nact = *snact;

    // thread owns samples chunk*1024 + g*512 + tid*4 + j (g=0..1, j=0..3)
    const float tb = (float)(chunk * ITEM_SAMP + tid * 4 + 1);
    ull TP[SPT / 2];
    TP[0] = pk2(tb,          tb + 1.0f);
    TP[1] = pk2(tb + 2.0f,   tb + 3.0f);
    TP[2] = pk2(tb + 512.0f, tb + 513.0f);
    TP[3] = pk2(tb + 514.0f, tb + 515.0f);

    ull ACC[SPT / 2];
    #pragma unroll
    for (int j = 0; j < SPT / 2; j++) ACC[j] = pk2(0.0f, 0.0f);

    int o = 0;
    for (; o + 1 < nact; o += 2) {                 // x2 unroll: 8 sin chains
        const ull fA = sfp[o],     aA = sap[o];
        const ull fB = sfp[o + 1], aB = sap[o + 1];
        #pragma unroll
        for (int j = 0; j < SPT / 2; j++) {
            OSC_STEP(fA, aA, TP[j], ACC[j]);
            OSC_STEP(fB, aB, TP[j], ACC[j]);
        }
    }
    if (o < nact) {
        const ull fA = sfp[o], aA = sap[o];
        #pragma unroll
        for (int j = 0; j < SPT / 2; j++)
            OSC_STEP(fA, aA, TP[j], ACC[j]);
    }

    float v0, v1, v2, v3, v4, v5, v6, v7;
    upk2(ACC[0], v0, v1); upk2(ACC[1], v2, v3);
    upk2(ACC[2], v4, v5); upk2(ACC[3], v6, v7);

    float4* o4 = (float4*)(out + be * NSAMP + chunk * ITEM_SAMP);
    float4 w0; w0.x = v0; w0.y = v1; w0.z = v2; w0.w = v3;
    float4 w1; w1.x = v4; w1.y = v5; w1.z = v6; w1.w = v7;
    o4[tid]       = w0;
    o4[tid + TPB] = w1;

    float m = fmaxf(fmaxf(fmaxf(fabsf(v0), fabsf(v1)),
                          fmaxf(fabsf(v2), fabsf(v3))),
                    fmaxf(fmaxf(fabsf(v4), fabsf(v5)),
                          fmaxf(fabsf(v6), fabsf(v7))));
    #pragma unroll
    for (int off = 16; off > 0; off >>= 1)
        m = fmaxf(m, __shfl_xor_sync(0xFFFFFFFFu, m, off));
    if (lane == 0) wm[tid >> 5] = m;
    __syncthreads();
    if (tid == 0) {
        float mm = fmaxf(fmaxf(wm[0], wm[1]), fmaxf(wm[2], wm[3]));
        g_wmax[it] = mm;
    }
    __syncthreads();                               // protect smem reuse
}

__global__ void __launch_bounds__(TPB, 7)          // reg cap 72 (~50 used):
fused_kernel(const float* __restrict__ f0_in,      // >=7 blk/SM -> 1036>=1024
             const float* __restrict__ dec_in,     // all co-resident, barrier
             const float* __restrict__ sp_in,      // deadlock-free
             float* __restrict__ out) {
    __shared__ ull   sfp[NOCT];
    __shared__ ull   sap[NOCT];
    __shared__ int   snact;
    __shared__ float wm[TPB / 32];
    __shared__ float sinv[BE];

    const int tid  = threadIdx.x;
    const int lane = tid & 31;

    const float INV2PI = 0.15915494309189535f;
    const float MAGIC  = 12582912.0f;              // 1.5 * 2^23
    const float HI     = 6.2831855f;               // fl32(2*pi)
    const float LO     = (float)(6.283185307179586476925286766559
                                 - (double)6.2831855f);
    const ull INV2PI2 = pk2(INV2PI, INV2PI);
    const ull MAGIC2  = pk2(MAGIC, MAGIC);
    const ull NMAG2   = pk2(-MAGIC, -MAGIC);
    const ull NHI2    = pk2(-HI, -HI);
    const ull NLO2    = pk2(-LO, -LO);

    // ---- Phase 1: two static items (different be's) per block ----
    do_item(2 * blockIdx.x, tid, lane, f0_in, dec_in, sp_in, out,
            sfp, sap, &snact, wm, INV2PI2, MAGIC2, NMAG2, NHI2, NLO2);
    do_item(2 * blockIdx.x + 1, tid, lane, f0_in, dec_in, sp_in, out,
            sfp, sap, &snact, wm, INV2PI2, MAGIC2, NMAG2, NHI2, NLO2);

    grid_barrier();   // all osc stores + g_wmax visible chip-wide

    // ---- Phase 2a: per-be inverse max (64 threads, 32 MLP'd L2 loads) ----
    if (tid < BE) {
        float m = 0.0f;
        #pragma unroll
        for (int j = 0; j < NITEMS / BE; j++)
            m = fmaxf(m, __ldcg(&g_wmax[(j << 6) + tid]));
        sinv[tid] = 1.0f / (m + 1e-8f);
    }
    __syncthreads();

    // ---- Phase 2b: grid-stride normalize, full-chip parallelism ----
    float4* o4 = (float4*)out;
    for (int i = blockIdx.x * TPB + tid; i < NF4; i += NBLK * TPB) {
        float inv = sinv[i >> 13];                  // 8192 float4 per be
        float4 w = __ldcg(o4 + i);                  // bypass stale L1
        w.x *= inv; w.y *= inv; w.z *= inv; w.w *= inv;
        __stcg(o4 + i, w);
    }
}

extern "C" void kernel_launch(void* const* d_in, const int* in_sizes, int n_in,
                              void* d_out, int out_size) {
    const float* f0  = (const float*)d_in[0];
    const float* dec = (const float*)d_in[1];
    const float* sp  = (const float*)d_in[2];
    float* out = (float*)d_out;

    fused_kernel<<<NBLK, TPB>>>(f0, dec, sp, out);
}